// round 7
// baseline (speedup 1.0000x reference)
#include <cuda_runtime.h>
#include <cuda_bf16.h>
#include <cstdint>
#include <math.h>

// Problem dims (fixed by the reference)
static constexpr int B_ROWS = 8192;
static constexpr int F_DIM  = 1024;
static constexpr int N_DIM  = 4096;

// Fallback GEMM tiling (legacy mma.sync path, verified in R1)
static constexpr int BM = 128, BN = 128, BK = 32;
static constexpr int PAD = 8;
static constexpr int LDT = BK + PAD;

// Safety margin for the float interval bounds (slack on real data is ~2.0)
static constexpr float EPS = 0.05f;

// Fused-kernel geometry
static constexpr int FUSED_BLOCKS = 592;   // 4 waves of 148
static constexpr int NORM_BLOCKS  = 228;   // ~ read-share of traffic (80/208)
static constexpr int TOT_ROWS     = 2 * B_ROWS + N_DIM;   // 20480 norm rows

// --------------------------- device scratch --------------------------------
__device__ __align__(16) __nv_bfloat16 g_xb[(size_t)B_ROWS * F_DIM];
__device__ __align__(16) __nv_bfloat16 g_yb[(size_t)B_ROWS * F_DIM];
__device__ __align__(16) __nv_bfloat16 g_wb[(size_t)N_DIM  * F_DIM];
__device__ float g_sumexp[B_ROWS];
__device__ float g_addvec[B_ROWS];
__device__ float g_rx[B_ROWS];               // ||x_i||
__device__ float g_ry[B_ROWS];               // ||y_i||
__device__ float g_rw[N_DIM];                // ||W_n||
__device__ int   g_any;                      // any row needs exact fallback?
__device__ int   g_blockfall[B_ROWS / BM];   // per-128-row-block fallback flag
__device__ int   g_done;                     // completion counter (self-reset)

// ---------------------------------------------------------------------------
// K1 (fused): row norms for x/y/W  +  output := 1.0f  +  flags tail.
//
// Blocks [0, NORM_BLOCKS): warp-per-row L2 norms (each lane: 8 float4, MLP=8).
// Blocks [NORM_BLOCKS, FUSED_BLOCKS): grid-stride float4 stores of 1.0f.
// The LAST block to finish (threadfence + atomic counter) computes
// max||y||, max||W||, max|bias|, runs the per-row saturation proof, writes
// g_blockfall / g_any, zeroes g_sumexp, and resets the counter for replay.
//
// Proof per row i (Cauchy-Schwarz, every term):
//   lse_i >= log(B) - ||x_i||*max_j||y_j|| = L;  L >= 3 ==> hswish(lse)=lse>=L
//   min_n(y_i.W_n + b_n) >= -(||y_i||*max_n||W_n|| + max|b|) = -bound
//   L - bound >= 1  ==> every element of output row i clips to exactly +1.0f
// ---------------------------------------------------------------------------
__global__ void __launch_bounds__(256)
k_fused(const float4* __restrict__ x, const float4* __restrict__ y,
        const float4* __restrict__ w, const float* __restrict__ bias,
        float4* __restrict__ out) {
    const int t = threadIdx.x;

    if (blockIdx.x < NORM_BLOCKS) {
        // ---- norm duty: warp-per-row, grid-stride over 20480 rows ----
        const int lane  = t & 31;
        const int warp0 = blockIdx.x * 8 + (t >> 5);
        const int nwarp = NORM_BLOCKS * 8;
        for (int gw = warp0; gw < TOT_ROWS; gw += nwarp) {
            const float4* src; float* dst; int row;
            if (gw < B_ROWS)          { src = x; dst = g_rx; row = gw; }
            else if (gw < 2 * B_ROWS) { src = y; dst = g_ry; row = gw - B_ROWS; }
            else                      { src = w; dst = g_rw; row = gw - 2 * B_ROWS; }
            const float4* p = src + (size_t)row * (F_DIM / 4);
            float s = 0.0f;
            #pragma unroll
            for (int j = 0; j < 8; j++) {
                float4 v = p[lane + 32 * j];
                s += v.x * v.x + v.y * v.y + v.z * v.z + v.w * v.w;
            }
            #pragma unroll
            for (int o = 16; o > 0; o >>= 1)
                s += __shfl_xor_sync(0xffffffffu, s, o);
            if (lane == 0) dst[row] = sqrtf(s);
        }
    } else {
        // ---- ones duty: stream 1.0f to the whole output ----
        const int n4    = B_ROWS * N_DIM / 4;
        const int nth   = (FUSED_BLOCKS - NORM_BLOCKS) * 256;
        const float4 one = make_float4(1.f, 1.f, 1.f, 1.f);
        for (int i = (blockIdx.x - NORM_BLOCKS) * 256 + t; i < n4; i += nth)
            out[i] = one;
    }

    // ---- completion counter: last block runs the flags tail ----
    __shared__ int s_last;
    __threadfence();
    __syncthreads();
    if (t == 0) {
        int old = atomicAdd(&g_done, 1);
        s_last = (old == FUSED_BLOCKS - 1) ? 1 : 0;
    }
    __syncthreads();
    if (!s_last) return;

    // ---- flags tail (one 256-thread block; all data L2-hot) ----
    __shared__ float r1[8], r2[8], r3[8];
    __shared__ int   sfall[B_ROWS / BM];
    __shared__ int   sany;
    __shared__ float sY, sW, sB;

    if (t < B_ROWS / BM) sfall[t] = 0;
    if (t == 0) sany = 0;

    float m1 = 0.f, m2 = 0.f, m3 = 0.f;
    for (int i = t; i < B_ROWS; i += 256) m1 = fmaxf(m1, g_ry[i]);
    for (int i = t; i < N_DIM;  i += 256) {
        m2 = fmaxf(m2, g_rw[i]);
        m3 = fmaxf(m3, fabsf(bias[i]));
    }
    #pragma unroll
    for (int o = 16; o > 0; o >>= 1) {
        m1 = fmaxf(m1, __shfl_xor_sync(0xffffffffu, m1, o));
        m2 = fmaxf(m2, __shfl_xor_sync(0xffffffffu, m2, o));
        m3 = fmaxf(m3, __shfl_xor_sync(0xffffffffu, m3, o));
    }
    if ((t & 31) == 0) { r1[t >> 5] = m1; r2[t >> 5] = m2; r3[t >> 5] = m3; }
    __syncthreads();
    if (t == 0) {
        float a = 0.f, b = 0.f, c = 0.f;
        #pragma unroll
        for (int i = 0; i < 8; i++) {
            a = fmaxf(a, r1[i]); b = fmaxf(b, r2[i]); c = fmaxf(c, r3[i]);
        }
        sY = a; sW = b; sB = c;
        g_done = 0;                       // reset for next graph replay
    }
    __syncthreads();

    const float Ymax = sY, Wmax = sW, bmax = sB;
    const float logB = logf((float)B_ROWS);
    for (int i = t; i < B_ROWS; i += 256) {
        const float L     = logB - g_rx[i] * Ymax;
        const float bound = g_ry[i] * Wmax + bmax;
        const bool  sat   = (L >= 3.0f + EPS) && (L - bound >= 1.0f + EPS);
        if (!sat) { atomicOr(&sfall[i >> 7], 1); atomicOr(&sany, 1); }
        g_sumexp[i] = 0.0f;
    }
    __syncthreads();
    if (t < B_ROWS / BM) g_blockfall[t] = sfall[t];
    if (t == 0) g_any = sany;
}

// ----------------------- exact fallback path (guarded) ---------------------
// Never taken when the saturation proof succeeds (all launches early-exit in
// ~1 wave). Kept fully correct for arbitrary data.
__global__ void k_convert_all(const float4* __restrict__ x,
                              const float4* __restrict__ y,
                              const float4* __restrict__ w) {
    if (g_any == 0) return;
    const int NX = B_ROWS * F_DIM / 4;
    const int NW = N_DIM * F_DIM / 4;
    int i  = blockIdx.x * blockDim.x + threadIdx.x;
    int st = gridDim.x * blockDim.x;
    for (; i < 2 * NX + NW; i += st) {
        const float4* src; __nv_bfloat162* dst; int k;
        if (i < NX)          { src = x; dst = (__nv_bfloat162*)g_xb; k = i; }
        else if (i < 2 * NX) { src = y; dst = (__nv_bfloat162*)g_yb; k = i - NX; }
        else                 { src = w; dst = (__nv_bfloat162*)g_wb; k = i - 2 * NX; }
        float4 v = src[k];
        dst[2*k]   = __floats2bfloat162_rn(v.x, v.y);
        dst[2*k+1] = __floats2bfloat162_rn(v.z, v.w);
    }
}

__global__ void k_finalize() {
    if (g_any == 0) return;
    int i = blockIdx.x * blockDim.x + threadIdx.x;
    for (; i < B_ROWS; i += gridDim.x * blockDim.x) {
        if (g_blockfall[i >> 7]) {
            float l = logf(g_sumexp[i]);
            g_addvec[i] = l * fminf(fmaxf(l + 3.0f, 0.0f), 6.0f) * (1.0f / 6.0f);
        }
    }
}

__device__ __forceinline__ uint32_t su32(const void* p) {
    return (uint32_t)__cvta_generic_to_shared(p);
}
__device__ __forceinline__ void cp_async16(void* smem, const void* gmem) {
    asm volatile("cp.async.cg.shared.global [%0], [%1], 16;\n"
                 :: "r"(su32(smem)), "l"(gmem));
}
__device__ __forceinline__ void ldsm_x4(uint32_t& r0, uint32_t& r1,
                                        uint32_t& r2, uint32_t& r3, uint32_t addr) {
    asm volatile("ldmatrix.sync.aligned.m8n8.x4.shared.b16 {%0,%1,%2,%3}, [%4];"
                 : "=r"(r0), "=r"(r1), "=r"(r2), "=r"(r3) : "r"(addr));
}
__device__ __forceinline__ void mma_bf16(float* c, const uint32_t* a, const uint32_t* b) {
    asm volatile(
        "mma.sync.aligned.m16n8k16.row.col.f32.bf16.bf16.f32 "
        "{%0,%1,%2,%3}, {%4,%5,%6,%7}, {%8,%9}, {%0,%1,%2,%3};"
        : "+f"(c[0]), "+f"(c[1]), "+f"(c[2]), "+f"(c[3])
        : "r"(a[0]), "r"(a[1]), "r"(a[2]), "r"(a[3]), "r"(b[0]), "r"(b[1]));
}
__device__ __forceinline__ float clamp1(float v) {
    return fminf(fmaxf(v, -1.0f), 1.0f);
}

// Persistent warp-tiled bf16 GEMM fallback (verified in R1).
// MODE 0: A=x, B=y, epilogue = sum(exp(score)) per row (atomic).
// MODE 1: A=y, B=W, epilogue = clamp(acc + bias[n] + addvec[b]).
template <int MODE>
__global__ void __launch_bounds__(256, 1)
k_gemm(const float* __restrict__ bias, float* __restrict__ out) {
    if (g_any == 0) return;

    __shared__ __nv_bfloat16 sA[2][BM * LDT];
    __shared__ __nv_bfloat16 sB[2][BN * LDT];
    __shared__ float s_sum[BM];

    const int tid    = threadIdx.x;
    const int lane   = tid & 31;
    const int warp   = tid >> 5;
    const int warp_m = warp & 1;
    const int warp_n = warp >> 1;
    const int g      = lane >> 2;
    const int t      = lane & 3;

    const int NTN     = (MODE == 0) ? (B_ROWS / BN) : (N_DIM / BN);
    const int n_tiles = (B_ROWS / BM) * NTN;

    for (int tile = blockIdx.x; tile < n_tiles; tile += gridDim.x) {
        const int tm = tile / NTN;
        const int tn = tile % NTN;
        if (!g_blockfall[tm]) continue;

        const int i0 = tm * BM;
        const int j0 = tn * BN;
        const __nv_bfloat16* Ag = ((MODE == 0) ? g_xb : g_yb) + (size_t)i0 * F_DIM;
        const __nv_bfloat16* Bg = ((MODE == 0) ? g_yb : g_wb) + (size_t)j0 * F_DIM;

        __syncthreads();
        if (MODE == 0 && tid < BM) s_sum[tid] = 0.0f;

        float acc[4][4][4];
        #pragma unroll
        for (int mf = 0; mf < 4; mf++)
            #pragma unroll
            for (int nf = 0; nf < 4; nf++)
                #pragma unroll
                for (int k = 0; k < 4; k++) acc[mf][nf][k] = 0.0f;

        auto load_tile = [&](int buf, int k0) {
            #pragma unroll
            for (int p = 0; p < 2; p++) {
                int chunk = tid + p * 256;
                int row = chunk >> 2, cc = chunk & 3;
                cp_async16(&sA[buf][row * LDT + cc * 8],
                           Ag + (size_t)row * F_DIM + k0 + cc * 8);
                cp_async16(&sB[buf][row * LDT + cc * 8],
                           Bg + (size_t)row * F_DIM + k0 + cc * 8);
            }
            asm volatile("cp.async.commit_group;\n");
        };

        const int NK = F_DIM / BK;
        load_tile(0, 0);

        for (int kt = 0; kt < NK; kt++) {
            const int buf = kt & 1;
            if (kt + 1 < NK) {
                load_tile(buf ^ 1, (kt + 1) * BK);
                asm volatile("cp.async.wait_group 1;\n");
            } else {
                asm volatile("cp.async.wait_group 0;\n");
            }
            __syncthreads();

            #pragma unroll
            for (int ks = 0; ks < 2; ks++) {
                uint32_t afr[4][4];
                uint32_t bfr[4][2];
                const int q = lane >> 3, r = lane & 7;
                #pragma unroll
                for (int mf = 0; mf < 4; mf++) {
                    int row = warp_m * 64 + mf * 16 + r + ((q & 1) ? 8 : 0);
                    int col = ks * 16 + ((q >= 2) ? 8 : 0);
                    ldsm_x4(afr[mf][0], afr[mf][1], afr[mf][2], afr[mf][3],
                            su32(&sA[buf][row * LDT + col]));
                }
                #pragma unroll
                for (int np = 0; np < 2; np++) {
                    int row = warp_n * 32 + np * 16 + r + (q >> 1) * 8;
                    int col = ks * 16 + (q & 1) * 8;
                    ldsm_x4(bfr[2*np][0], bfr[2*np][1], bfr[2*np+1][0], bfr[2*np+1][1],
                            su32(&sB[buf][row * LDT + col]));
                }
                #pragma unroll
                for (int mf = 0; mf < 4; mf++)
                    #pragma unroll
                    for (int nf = 0; nf < 4; nf++)
                        mma_bf16(acc[mf][nf], afr[mf], bfr[nf]);
            }
            __syncthreads();
        }

        if (MODE == 0) {
            #pragma unroll
            for (int mf = 0; mf < 4; mf++) {
                float v0 = 0.0f, v1 = 0.0f;
                #pragma unroll
                for (int nf = 0; nf < 4; nf++) {
                    v0 += __expf(acc[mf][nf][0]) + __expf(acc[mf][nf][1]);
                    v1 += __expf(acc[mf][nf][2]) + __expf(acc[mf][nf][3]);
                }
                v0 += __shfl_xor_sync(0xffffffffu, v0, 1);
                v0 += __shfl_xor_sync(0xffffffffu, v0, 2);
                v1 += __shfl_xor_sync(0xffffffffu, v1, 1);
                v1 += __shfl_xor_sync(0xffffffffu, v1, 2);
                if (t == 0) {
                    atomicAdd(&s_sum[warp_m * 64 + mf * 16 + g],     v0);
                    atomicAdd(&s_sum[warp_m * 64 + mf * 16 + 8 + g], v1);
                }
            }
            __syncthreads();
            if (tid < BM) atomicAdd(&g_sumexp[i0 + tid], s_sum[tid]);
        } else {
            #pragma unroll
            for (int mf = 0; mf < 4; mf++) {
                int r0 = i0 + warp_m * 64 + mf * 16 + g;
                float av0 = g_addvec[r0];
                float av1 = g_addvec[r0 + 8];
                #pragma unroll
                for (int nf = 0; nf < 4; nf++) {
                    int c = j0 + warp_n * 32 + nf * 8 + 2 * t;
                    float b0 = bias[c], b1 = bias[c + 1];
                    float2 o0, o1;
                    o0.x = clamp1(acc[mf][nf][0] + b0 + av0);
                    o0.y = clamp1(acc[mf][nf][1] + b1 + av0);
                    o1.x = clamp1(acc[mf][nf][2] + b0 + av1);
                    o1.y = clamp1(acc[mf][nf][3] + b1 + av1);
                    *(float2*)&out[(size_t)r0 * N_DIM + c]       = o0;
                    *(float2*)&out[(size_t)(r0 + 8) * N_DIM + c] = o1;
                }
            }
        }
    }
}

// ---------------------------------------------------------------------------
// Launch sequence (graph-capturable: kernel launches only)
// ---------------------------------------------------------------------------
extern "C" void kernel_launch(void* const* d_in, const int* in_sizes, int n_in,
                              void* d_out, int out_size) {
    const float* x    = (const float*)d_in[0];  // [8192,1024]
    const float* y    = (const float*)d_in[1];  // [8192,1024]
    const float* w    = (const float*)d_in[2];  // [4096,1024]
    const float* bias = (const float*)d_in[3];  // [4096]
    float* out = (float*)d_out;                 // [8192,4096]

    // 1) fused: norms + ones-fill + saturation proof (last block)
    k_fused<<<FUSED_BLOCKS, 256>>>((const float4*)x, (const float4*)y,
                                   (const float4*)w, bias, (float4*)out);

    // 2-5) exact fallback, guarded (each ~1 wave of early-exit when proven)
    k_convert_all<<<148, 256>>>((const float4*)x, (const float4*)y,
                                (const float4*)w);
    k_gemm<0><<<148, 256>>>(bias, out);
    k_finalize<<<8, 1024>>>();
    k_gemm<1><<<148, 256>>>(bias, out);
}

// round 8
// speedup vs baseline: 1.3871x; 1.3871x over previous
#include <cuda_runtime.h>
#include <cuda_bf16.h>
#include <cstdint>
#include <math.h>

// Problem dims (fixed by the reference)
static constexpr int B_ROWS = 8192;
static constexpr int F_DIM  = 1024;
static constexpr int N_DIM  = 4096;

// Fallback GEMM tiling (legacy mma.sync path, verified in R1)
static constexpr int BM = 128, BN = 128, BK = 32;
static constexpr int PAD = 8;
static constexpr int LDT = BK + PAD;

// Safety margin for the float interval bounds (slack on real data is ~2.0)
static constexpr float EPS = 0.05f;

static constexpr int GRID_MAIN = 148;       // all-resident (1 block/SM)
static constexpr int TOT_ROWS  = 2 * B_ROWS + N_DIM;   // 20480 norm rows

// --------------------------- device scratch --------------------------------
__device__ __align__(16) __nv_bfloat16 g_xb[(size_t)B_ROWS * F_DIM];
__device__ __align__(16) __nv_bfloat16 g_yb[(size_t)B_ROWS * F_DIM];
__device__ __align__(16) __nv_bfloat16 g_wb[(size_t)N_DIM  * F_DIM];
__device__ float g_sumexp[B_ROWS];
__device__ float g_addvec[B_ROWS];
__device__ float g_rx[B_ROWS];               // ||x_i||
__device__ float g_ry[B_ROWS];               // ||y_i||
__device__ float g_rw[N_DIM];                // ||W_n||
__device__ float g_pY[GRID_MAIN];            // per-block max ||y||
__device__ float g_pW[GRID_MAIN];            // per-block max ||W||
__device__ int   g_any;                      // any row needs exact fallback?
__device__ int   g_blockfall[B_ROWS / BM];   // per-128-row-block fallback flag

// Self-resetting sense-reversal grid barrier (safe: grid == 148 all-resident)
__device__ unsigned          g_bar_count = 0;
__device__ volatile unsigned g_bar_sense = 0;

__device__ __forceinline__ void grid_sync(unsigned nblk) {
    __syncthreads();
    if (threadIdx.x == 0) {
        __threadfence();
        unsigned old = g_bar_sense;
        if (atomicAdd(&g_bar_count, 1u) == nblk - 1u) {
            g_bar_count = 0;
            __threadfence();
            g_bar_sense = old ^ 1u;
        } else {
            while (g_bar_sense == old) { __nanosleep(64); }
        }
    }
    __syncthreads();
}

// ---------------------------------------------------------------------------
// K1: norms (sound, all 20480 rows)  ->  grid barrier  ->
//     blocks 0-7: maxes + saturation proof + flags;  all blocks: ones-fill.
//
// Proof per row i (Cauchy-Schwarz on every term):
//   lse_i >= log(B) - ||x_i||*max_j||y_j|| = L;  L>=3 ==> hswish(lse)=lse>=L
//   min_n(y_i.W_n + b_n) >= -(||y_i||*max_n||W_n|| + max|b|) = -bound
//   L - bound >= 1  ==> every element of output row i clips to exactly +1.0f
// ---------------------------------------------------------------------------
__global__ void __launch_bounds__(1024, 1)
k_main(const float4* __restrict__ x, const float4* __restrict__ y,
       const float4* __restrict__ w, const float* __restrict__ bias,
       float4* __restrict__ out) {
    const int t    = threadIdx.x;
    const int wid  = t >> 5;
    const int lane = t & 31;

    __shared__ float smA[32], smB_[32], smC[32];
    __shared__ float sY, sW, sB;
    __shared__ int   sfall[8];

    if (blockIdx.x == GRID_MAIN - 1 && t == 0) g_any = 0;

    // ---- Phase A: warp-per-row L2 norms over x (8192), y (8192), W (4096)
    float mY = 0.f, mW = 0.f;
    const int gw0 = blockIdx.x * 32 + wid;
    for (int gw = gw0; gw < TOT_ROWS; gw += GRID_MAIN * 32) {
        const float4* src; float* dst; int row, kind;
        if (gw < B_ROWS)          { src = x; dst = g_rx; row = gw;              kind = 0; }
        else if (gw < 2 * B_ROWS) { src = y; dst = g_ry; row = gw - B_ROWS;     kind = 1; }
        else                      { src = w; dst = g_rw; row = gw - 2 * B_ROWS; kind = 2; }
        const float4* p = src + (size_t)row * (F_DIM / 4);
        float s = 0.f;
        #pragma unroll
        for (int j = 0; j < 8; j++) {
            float4 v = p[lane + 32 * j];
            s += v.x * v.x + v.y * v.y + v.z * v.z + v.w * v.w;
        }
        #pragma unroll
        for (int o = 16; o > 0; o >>= 1) s += __shfl_xor_sync(0xffffffffu, s, o);
        if (lane == 0) {
            float nrm = sqrtf(s);
            dst[row] = nrm;
            if (kind == 1)      mY = fmaxf(mY, nrm);
            else if (kind == 2) mW = fmaxf(mW, nrm);
        }
    }
    if (lane == 0) { smA[wid] = mY; smB_[wid] = mW; }
    __syncthreads();
    if (wid == 0) {
        float a = smA[lane], b = smB_[lane];
        #pragma unroll
        for (int o = 16; o > 0; o >>= 1) {
            a = fmaxf(a, __shfl_xor_sync(0xffffffffu, a, o));
            b = fmaxf(b, __shfl_xor_sync(0xffffffffu, b, o));
        }
        if (lane == 0) { g_pY[blockIdx.x] = a; g_pW[blockIdx.x] = b; }
    }

    grid_sync(GRID_MAIN);

    // ---- Phase B: blocks 0-7 run the proof (1024 rows each); all L2-hot
    if (blockIdx.x < 8) {
        float a = 0.f, b = 0.f, c = 0.f;
        for (int i = t; i < GRID_MAIN; i += 1024) {
            a = fmaxf(a, g_pY[i]); b = fmaxf(b, g_pW[i]);
        }
        for (int i = t; i < N_DIM; i += 1024) c = fmaxf(c, fabsf(bias[i]));
        #pragma unroll
        for (int o = 16; o > 0; o >>= 1) {
            a = fmaxf(a, __shfl_xor_sync(0xffffffffu, a, o));
            b = fmaxf(b, __shfl_xor_sync(0xffffffffu, b, o));
            c = fmaxf(c, __shfl_xor_sync(0xffffffffu, c, o));
        }
        if (lane == 0) { smA[wid] = a; smB_[wid] = b; smC[wid] = c; }
        if (t < 8) sfall[t] = 0;
        __syncthreads();
        if (t == 0) {
            float ra = 0.f, rb = 0.f, rc = 0.f;
            #pragma unroll
            for (int i = 0; i < 32; i++) {
                ra = fmaxf(ra, smA[i]); rb = fmaxf(rb, smB_[i]); rc = fmaxf(rc, smC[i]);
            }
            sY = ra; sW = rb; sB = rc;
        }
        __syncthreads();

        const int   row   = blockIdx.x * 1024 + t;
        const float L     = logf((float)B_ROWS) - g_rx[row] * sY;
        const float bound = g_ry[row] * sW + sB;
        const bool  sat   = (L >= 3.0f + EPS) && (L - bound >= 1.0f + EPS);
        if (!sat) { atomicOr(&sfall[t >> 7], 1); atomicOr(&g_any, 1); }
        g_sumexp[row] = 0.0f;
        __syncthreads();
        if (t < 8) g_blockfall[blockIdx.x * 8 + t] = sfall[t];
    }

    // ---- Phase C: all blocks stream +1.0f to the output (proven value)
    const int n4 = B_ROWS * N_DIM / 4;
    const float4 one = make_float4(1.f, 1.f, 1.f, 1.f);
    for (int i = blockIdx.x * 1024 + t; i < n4; i += GRID_MAIN * 1024)
        out[i] = one;
}

// ----------------------- exact fallback path (guarded) ---------------------
__device__ __forceinline__ uint32_t su32(const void* p) {
    return (uint32_t)__cvta_generic_to_shared(p);
}
__device__ __forceinline__ void cp_async16(void* smem, const void* gmem) {
    asm volatile("cp.async.cg.shared.global [%0], [%1], 16;\n"
                 :: "r"(su32(smem)), "l"(gmem));
}
__device__ __forceinline__ void ldsm_x4(uint32_t& r0, uint32_t& r1,
                                        uint32_t& r2, uint32_t& r3, uint32_t addr) {
    asm volatile("ldmatrix.sync.aligned.m8n8.x4.shared.b16 {%0,%1,%2,%3}, [%4];"
                 : "=r"(r0), "=r"(r1), "=r"(r2), "=r"(r3) : "r"(addr));
}
__device__ __forceinline__ void mma_bf16(float* c, const uint32_t* a, const uint32_t* b) {
    asm volatile(
        "mma.sync.aligned.m16n8k16.row.col.f32.bf16.bf16.f32 "
        "{%0,%1,%2,%3}, {%4,%5,%6,%7}, {%8,%9}, {%0,%1,%2,%3};"
        : "+f"(c[0]), "+f"(c[1]), "+f"(c[2]), "+f"(c[3])
        : "r"(a[0]), "r"(a[1]), "r"(a[2]), "r"(a[3]), "r"(b[0]), "r"(b[1]));
}
__device__ __forceinline__ float clamp1(float v) {
    return fminf(fmaxf(v, -1.0f), 1.0f);
}

// Warp-tiled bf16 GEMM phase (verified in R1), persistent over tiles.
// MODE 0: A=x, B=y, epilogue = sum(exp(score)) per row (atomic into g_sumexp)
// MODE 1: A=y, B=W, epilogue = clamp(acc + bias[n] + addvec[b]) -> out
template <int MODE>
__device__ void gemm_phase(const float* __restrict__ bias, float* __restrict__ out,
                           __nv_bfloat16 (*sA)[BM * LDT],
                           __nv_bfloat16 (*sB)[BN * LDT],
                           float* s_sum) {
    const int tid    = threadIdx.x;
    const int lane   = tid & 31;
    const int warp   = tid >> 5;
    const int warp_m = warp & 1;
    const int warp_n = warp >> 1;
    const int g      = lane >> 2;
    const int t      = lane & 3;

    const int NTN     = (MODE == 0) ? (B_ROWS / BN) : (N_DIM / BN);
    const int n_tiles = (B_ROWS / BM) * NTN;

    for (int tile = blockIdx.x; tile < n_tiles; tile += gridDim.x) {
        const int tm = tile / NTN;
        const int tn = tile % NTN;
        if (!g_blockfall[tm]) continue;

        const int i0 = tm * BM;
        const int j0 = tn * BN;
        const __nv_bfloat16* Ag = ((MODE == 0) ? g_xb : g_yb) + (size_t)i0 * F_DIM;
        const __nv_bfloat16* Bg = ((MODE == 0) ? g_yb : g_wb) + (size_t)j0 * F_DIM;

        __syncthreads();
        if (MODE == 0 && tid < BM) s_sum[tid] = 0.0f;

        float acc[4][4][4];
        #pragma unroll
        for (int mf = 0; mf < 4; mf++)
            #pragma unroll
            for (int nf = 0; nf < 4; nf++)
                #pragma unroll
                for (int k = 0; k < 4; k++) acc[mf][nf][k] = 0.0f;

        auto load_tile = [&](int buf, int k0) {
            #pragma unroll
            for (int p = 0; p < 2; p++) {
                int chunk = tid + p * 256;
                int row = chunk >> 2, cc = chunk & 3;
                cp_async16(&sA[buf][row * LDT + cc * 8],
                           Ag + (size_t)row * F_DIM + k0 + cc * 8);
                cp_async16(&sB[buf][row * LDT + cc * 8],
                           Bg + (size_t)row * F_DIM + k0 + cc * 8);
            }
            asm volatile("cp.async.commit_group;\n");
        };

        const int NK = F_DIM / BK;
        load_tile(0, 0);

        for (int kt = 0; kt < NK; kt++) {
            const int buf = kt & 1;
            if (kt + 1 < NK) {
                load_tile(buf ^ 1, (kt + 1) * BK);
                asm volatile("cp.async.wait_group 1;\n");
            } else {
                asm volatile("cp.async.wait_group 0;\n");
            }
            __syncthreads();

            #pragma unroll
            for (int ks = 0; ks < 2; ks++) {
                uint32_t afr[4][4];
                uint32_t bfr[4][2];
                const int q = lane >> 3, r = lane & 7;
                #pragma unroll
                for (int mf = 0; mf < 4; mf++) {
                    int row = warp_m * 64 + mf * 16 + r + ((q & 1) ? 8 : 0);
                    int col = ks * 16 + ((q >= 2) ? 8 : 0);
                    ldsm_x4(afr[mf][0], afr[mf][1], afr[mf][2], afr[mf][3],
                            su32(&sA[buf][row * LDT + col]));
                }
                #pragma unroll
                for (int np = 0; np < 2; np++) {
                    int row = warp_n * 32 + np * 16 + r + (q >> 1) * 8;
                    int col = ks * 16 + (q & 1) * 8;
                    ldsm_x4(bfr[2*np][0], bfr[2*np][1], bfr[2*np+1][0], bfr[2*np+1][1],
                            su32(&sB[buf][row * LDT + col]));
                }
                #pragma unroll
                for (int mf = 0; mf < 4; mf++)
                    #pragma unroll
                    for (int nf = 0; nf < 4; nf++)
                        mma_bf16(acc[mf][nf], afr[mf], bfr[nf]);
            }
            __syncthreads();
        }

        if (MODE == 0) {
            #pragma unroll
            for (int mf = 0; mf < 4; mf++) {
                float v0 = 0.0f, v1 = 0.0f;
                #pragma unroll
                for (int nf = 0; nf < 4; nf++) {
                    v0 += __expf(acc[mf][nf][0]) + __expf(acc[mf][nf][1]);
                    v1 += __expf(acc[mf][nf][2]) + __expf(acc[mf][nf][3]);
                }
                v0 += __shfl_xor_sync(0xffffffffu, v0, 1);
                v0 += __shfl_xor_sync(0xffffffffu, v0, 2);
                v1 += __shfl_xor_sync(0xffffffffu, v1, 1);
                v1 += __shfl_xor_sync(0xffffffffu, v1, 2);
                if (t == 0) {
                    atomicAdd(&s_sum[warp_m * 64 + mf * 16 + g],     v0);
                    atomicAdd(&s_sum[warp_m * 64 + mf * 16 + 8 + g], v1);
                }
            }
            __syncthreads();
            if (tid < BM) atomicAdd(&g_sumexp[i0 + tid], s_sum[tid]);
        } else {
            #pragma unroll
            for (int mf = 0; mf < 4; mf++) {
                int r0 = i0 + warp_m * 64 + mf * 16 + g;
                float av0 = g_addvec[r0];
                float av1 = g_addvec[r0 + 8];
                #pragma unroll
                for (int nf = 0; nf < 4; nf++) {
                    int c = j0 + warp_n * 32 + nf * 8 + 2 * t;
                    float b0 = bias[c], b1 = bias[c + 1];
                    float2 o0, o1;
                    o0.x = clamp1(acc[mf][nf][0] + b0 + av0);
                    o0.y = clamp1(acc[mf][nf][1] + b1 + av0);
                    o1.x = clamp1(acc[mf][nf][2] + b0 + av1);
                    o1.y = clamp1(acc[mf][nf][3] + b1 + av1);
                    *(float2*)&out[(size_t)r0 * N_DIM + c]       = o0;
                    *(float2*)&out[(size_t)(r0 + 8) * N_DIM + c] = o1;
                }
            }
        }
    }
}

// K2: merged exact fallback (convert -> gemm0 -> finalize -> gemm1) with
// internal grid barriers. Never taken when the proof succeeds (exits after
// one flag load). Fully correct for arbitrary data. 148 blocks all-resident.
__global__ void __launch_bounds__(256, 1)
k_fallback(const float4* __restrict__ x, const float4* __restrict__ y,
           const float4* __restrict__ w, const float* __restrict__ bias,
           float* __restrict__ out) {
    if (g_any == 0) return;

    __shared__ __nv_bfloat16 sA[2][BM * LDT];
    __shared__ __nv_bfloat16 sB[2][BN * LDT];
    __shared__ float s_sum[BM];

    const int t = threadIdx.x;

    // P1: fp32 -> bf16 for x, y, W
    {
        const int NX = B_ROWS * F_DIM / 4;
        const int NW = N_DIM * F_DIM / 4;
        int i  = blockIdx.x * 256 + t;
        int st = gridDim.x * 256;
        for (; i < 2 * NX + NW; i += st) {
            const float4* src; __nv_bfloat162* dst; int k;
            if (i < NX)          { src = x; dst = (__nv_bfloat162*)g_xb; k = i; }
            else if (i < 2 * NX) { src = y; dst = (__nv_bfloat162*)g_yb; k = i - NX; }
            else                 { src = w; dst = (__nv_bfloat162*)g_wb; k = i - 2 * NX; }
            float4 v = src[k];
            dst[2*k]   = __floats2bfloat162_rn(v.x, v.y);
            dst[2*k+1] = __floats2bfloat162_rn(v.z, v.w);
        }
    }
    grid_sync(GRID_MAIN);

    // P2: scores GEMM + sum(exp) rows
    gemm_phase<0>(bias, out, sA, sB, s_sum);
    grid_sync(GRID_MAIN);

    // P3: addvec = hardswish(log(sumexp)) for fallback rows
    for (int i = blockIdx.x * 256 + t; i < B_ROWS; i += gridDim.x * 256) {
        if (g_blockfall[i >> 7]) {
            float l = logf(g_sumexp[i]);
            g_addvec[i] = l * fminf(fmaxf(l + 3.0f, 0.0f), 6.0f) * (1.0f / 6.0f);
        }
    }
    grid_sync(GRID_MAIN);

    // P4: output GEMM + bias + addvec + clamp
    gemm_phase<1>(bias, out, sA, sB, s_sum);
}

// ---------------------------------------------------------------------------
// Launch sequence (graph-capturable: kernel launches only)
// ---------------------------------------------------------------------------
extern "C" void kernel_launch(void* const* d_in, const int* in_sizes, int n_in,
                              void* d_out, int out_size) {
    const float* x    = (const float*)d_in[0];  // [8192,1024]
    const float* y    = (const float*)d_in[1];  // [8192,1024]
    const float* w    = (const float*)d_in[2];  // [4096,1024]
    const float* bias = (const float*)d_in[3];  // [4096]
    float* out = (float*)d_out;                 // [8192,4096]

    // 1) norms + barrier + proof/flags + ones-fill (one kernel)
    k_main<<<GRID_MAIN, 1024>>>((const float4*)x, (const float4*)y,
                                (const float4*)w, bias, (float4*)out);

    // 2) exact fallback (guarded; exits immediately when proof succeeded)
    k_fallback<<<GRID_MAIN, 256>>>((const float4*)x, (const float4*)y,
                                   (const float4*)w, bias, out);
}